// round 14
// baseline (speedup 1.0000x reference)
#include <cuda_runtime.h>
#include <cuda_bf16.h>
#include <math.h>

#define S      15
#define BATCH  32
#define NNODE  5000
#define NEDGE  80000
#define NEDGE_SL (NEDGE + NNODE)
#define FIN    16
#define HID    512
#define G3     1536
#define SB     (S*BATCH)
#define K5     5000
#define K5P    5088
#define MP     512
#define KCH    159
#define KSPL   3
#define KCPS   53
#define BH     (BATCH*HID)
#define SLC    3
#define GCN_CTAS (SB / SLC)
#define WCONV_CTAS 40
#define PREP_CTAS 313

typedef unsigned long long ull;

struct __align__(8) Edge { int s; float w; };

__device__ int   g_indeg[NNODE];
__device__ int   g_off[NNODE + 1];
__device__ int   g_pos[NNODE];
__device__ float g_dinv[NNODE];
__device__ Edge  g_edges[NEDGE_SL];
__device__ int   g_is64;
__device__ int   g_syncA, g_syncB, g_syncC;

__device__ __nv_bfloat16 g_ghi[MP * K5P];
__device__ __nv_bfloat16 g_glo[MP * K5P];
__device__ __nv_bfloat16 g_whi[G3 * K5P];
__device__ __nv_bfloat16 g_wlo[G3 * K5P];

__device__ float g_gi0[SB * G3];
__device__ float g_gi1[S * BATCH * G3];
__device__ float g_h0s[(S + 1) * BH];
__device__ float g_h1s[(S + 1) * BH];
__device__ int   g_f0[S], g_f1[S], g_f2[S];

#define FFMA2(c, a, b) asm("fma.rn.f32x2 %0, %1, %2, %0;" : "+l"(c) : "l"(a), "l"(b))
__device__ __forceinline__ float hsum2(ull v) {
    float lo, hi;
    asm("mov.b64 {%0,%1}, %2;" : "=f"(lo), "=f"(hi) : "l"(v));
    return lo + hi;
}
__device__ __forceinline__ unsigned smem_u32(const void* p) {
    return (unsigned)__cvta_generic_to_shared(p);
}
__device__ __forceinline__ void ldm_x4(unsigned a, unsigned& r0, unsigned& r1,
                                       unsigned& r2, unsigned& r3) {
    asm volatile("ldmatrix.sync.aligned.m8n8.x4.shared.b16 {%0,%1,%2,%3}, [%4];"
                 : "=r"(r0), "=r"(r1), "=r"(r2), "=r"(r3) : "r"(a));
}
__device__ __forceinline__ void mma_bf16(float* d, const unsigned* a, const unsigned* b) {
    asm volatile(
        "mma.sync.aligned.m16n8k16.row.col.f32.bf16.bf16.f32 "
        "{%0,%1,%2,%3}, {%4,%5,%6,%7}, {%8,%9}, {%0,%1,%2,%3};"
        : "+f"(d[0]), "+f"(d[1]), "+f"(d[2]), "+f"(d[3])
        : "r"(a[0]), "r"(a[1]), "r"(a[2]), "r"(a[3]), "r"(b[0]), "r"(b[1]));
}
__device__ __forceinline__ void spin_ge(const int* p, int n) {
    int v;
    do {
        asm volatile("ld.acquire.gpu.b32 %0, [%1];" : "=r"(v) : "l"(p));
        if (v < n) __nanosleep(32);
    } while (v < n);
}
__device__ __forceinline__ void spin32(const int* p) { spin_ge(p, 32); }
__device__ __forceinline__ void red_release(int* p) {
    asm volatile("red.release.gpu.global.add.s32 [%0], %1;" :: "l"(p), "r"(1) : "memory");
}

// ---------------- merged prep (unchanged R13) ----------------
__global__ __launch_bounds__(256) void prep_kernel(const int* __restrict__ ei) {
    int tid = threadIdx.x;
    int gid = blockIdx.x * 256 + tid;

    if (gid == 0) {
        int f = 1;
        for (int q = 0; q < 64; q++) if (ei[2 * q + 1] != 0) { f = 0; break; }
        g_is64 = f;
    }
    if (gid < NNODE) g_indeg[gid] = 1;
    if (gid < BH) { g_h0s[gid] = 0.f; g_h1s[gid] = 0.f; }
    if (gid < S) { g_f0[gid] = 0; g_f1[gid] = 0; g_f2[gid] = 0; }
    __syncthreads();
    if (tid == 0) { red_release(&g_syncA); spin_ge(&g_syncA, PREP_CTAS); }
    __syncthreads();

    if (gid < NEDGE) {
        int t = g_is64 ? ei[2 * (NEDGE + gid)] : ei[NEDGE + gid];
        atomicAdd(&g_indeg[t], 1);
    }
    __syncthreads();
    if (tid == 0) { red_release(&g_syncB); spin_ge(&g_syncB, PREP_CTAS); }
    __syncthreads();

    if (blockIdx.x == 0) {
        __shared__ int ssum[256];
        int vals[20]; int s = 0;
        #pragma unroll
        for (int q = 0; q < 20; q++) {
            int idx = tid * 20 + q;
            vals[q] = (idx < NNODE) ? g_indeg[idx] : 0;
            s += vals[q];
        }
        ssum[tid] = s;
        __syncthreads();
        for (int off = 1; off < 256; off <<= 1) {
            int v = (tid >= off) ? ssum[tid - off] : 0;
            __syncthreads();
            ssum[tid] += v;
            __syncthreads();
        }
        int run = ssum[tid] - s;
        #pragma unroll
        for (int q = 0; q < 20; q++) {
            int idx = tid * 20 + q;
            if (idx < NNODE) {
                g_off[idx] = run; g_pos[idx] = run;
                g_dinv[idx] = rsqrtf((float)vals[q]);
                run += vals[q];
            }
        }
        if (tid == 255) g_off[NNODE] = ssum[255];
        __syncthreads();
        if (tid == 0) red_release(&g_syncC);
    }
    if (tid == 0) spin_ge(&g_syncC, 1);
    __syncthreads();

    for (int e = gid; e < NEDGE_SL; e += PREP_CTAS * 256) {
        int is64 = g_is64;
        int s, t;
        if (e < NEDGE) {
            s = is64 ? ei[2 * e] : ei[e];
            t = is64 ? ei[2 * (NEDGE + e)] : ei[NEDGE + e];
        } else { s = t = e - NEDGE; }
        int idx = atomicAdd(&g_pos[t], 1);
        Edge E; E.s = s; E.w = g_dinv[s] * g_dinv[t];
        g_edges[idx] = E;
    }
}

// ---------------- fused GCN + wconv + gi0 bias prefill (unchanged R13) ----------------
#define SMEM_GCN ((NNODE * 6 + NNODE * 3) * 4)

__global__ __launch_bounds__(1024) void gcn_kernel(const float* __restrict__ x,
                                                   const float* __restrict__ W1,
                                                   const float* __restrict__ b1,
                                                   const float* __restrict__ W2,
                                                   const float* __restrict__ b2,
                                                   const float* __restrict__ wih0,
                                                   const float* __restrict__ bih0) {
    int cta = blockIdx.x, tid = threadIdx.x;

    if (cta >= GCN_CTAS) {
        if (cta == GCN_CTAS && tid == 0) {
            g_syncA = 0; g_syncB = 0; g_syncC = 0;
        }
        int base = (cta - GCN_CTAS) * 1024 + tid;
        for (int i = base; i < G3 * K5; i += WCONV_CTAS * 1024) {
            int n = i / K5, k = i - n * K5;
            float v = wih0[i];
            __nv_bfloat16 hi = __float2bfloat16(v);
            g_whi[(size_t)n * K5P + k] = hi;
            g_wlo[(size_t)n * K5P + k] = __float2bfloat16(v - __bfloat162float(hi));
        }
        for (int i = base; i < SB * G3; i += WCONV_CTAS * 1024)
            g_gi0[i] = bih0[i % G3];
        return;
    }

    extern __shared__ float sm[];
    float* hA = sm;
    float* h2 = sm + NNODE * 6;
    __shared__ float s_w1[SLC][FIN][2];
    __shared__ float s_b1[SLC][2], s_w2[SLC][2], s_b2[SLC];

    if (tid < SLC * FIN * 2) {
        int sl = tid / (FIN * 2), rem = tid % (FIN * 2);
        int s = (cta * SLC + sl) >> 5;
        s_w1[sl][rem >> 1][rem & 1] = W1[s * (FIN * 2) + rem];
    }
    if (tid >= 128 && tid < 128 + SLC * 2) {
        int q = tid - 128; int sl = q >> 1, c = q & 1;
        int s = (cta * SLC + sl) >> 5;
        s_b1[sl][c] = b1[s * 2 + c];
        s_w2[sl][c] = W2[s * 2 + c];
    }
    if (tid >= 160 && tid < 160 + SLC) {
        int sl = tid - 160;
        s_b2[sl] = b2[((cta * SLC + sl) >> 5)];
    }
    __syncthreads();

    for (int idx = tid; idx < SLC * NNODE; idx += 1024) {
        int sl = idx / NNODE, n = idx - sl * NNODE;
        const float4* xp = (const float4*)(x + ((size_t)(cta * SLC + sl) * NNODE + n) * FIN);
        float xv[16];
        *(float4*)&xv[0] = xp[0]; *(float4*)&xv[4] = xp[1];
        *(float4*)&xv[8] = xp[2]; *(float4*)&xv[12] = xp[3];
        float a0 = 0.f, a1 = 0.f;
        #pragma unroll
        for (int f = 0; f < FIN; f++) {
            a0 += xv[f] * s_w1[sl][f][0];
            a1 += xv[f] * s_w1[sl][f][1];
        }
        hA[n * 6 + sl * 2]     = a0;
        hA[n * 6 + sl * 2 + 1] = a1;
    }
    __syncthreads();

    int warp = tid >> 5, lane = tid & 31;
    int seg = lane >> 3, sub = lane & 7;

    for (int n0 = warp * 4; n0 < NNODE; n0 += 128) {
        int n = n0 + seg;
        int e0 = g_off[n], e1 = g_off[n + 1];
        float ac0 = 0.f, ac1 = 0.f, ac2 = 0.f, ac3 = 0.f, ac4 = 0.f, ac5 = 0.f;
        for (int e = e0 + sub; e < e1; e += 8) {
            Edge E = g_edges[e];
            const float2* src = (const float2*)(hA + E.s * 6);
            float2 p0 = src[0], p1 = src[1], p2 = src[2];
            ac0 += E.w * p0.x; ac1 += E.w * p0.y;
            ac2 += E.w * p1.x; ac3 += E.w * p1.y;
            ac4 += E.w * p2.x; ac5 += E.w * p2.y;
        }
        #pragma unroll
        for (int m = 4; m >= 1; m >>= 1) {
            ac0 += __shfl_xor_sync(0xFFFFFFFF, ac0, m);
            ac1 += __shfl_xor_sync(0xFFFFFFFF, ac1, m);
            ac2 += __shfl_xor_sync(0xFFFFFFFF, ac2, m);
            ac3 += __shfl_xor_sync(0xFFFFFFFF, ac3, m);
            ac4 += __shfl_xor_sync(0xFFFFFFFF, ac4, m);
            ac5 += __shfl_xor_sync(0xFFFFFFFF, ac5, m);
        }
        if (sub == 0) {
            float r0, r1;
            r0 = fmaxf(ac0 + s_b1[0][0], 0.f); r1 = fmaxf(ac1 + s_b1[0][1], 0.f);
            h2[n * 3 + 0] = r0 * s_w2[0][0] + r1 * s_w2[0][1];
            r0 = fmaxf(ac2 + s_b1[1][0], 0.f); r1 = fmaxf(ac3 + s_b1[1][1], 0.f);
            h2[n * 3 + 1] = r0 * s_w2[1][0] + r1 * s_w2[1][1];
            r0 = fmaxf(ac4 + s_b1[2][0], 0.f); r1 = fmaxf(ac5 + s_b1[2][1], 0.f);
            h2[n * 3 + 2] = r0 * s_w2[2][0] + r1 * s_w2[2][1];
        }
    }
    __syncthreads();

    for (int n0 = warp * 4; n0 < NNODE; n0 += 128) {
        int n = n0 + seg;
        int e0 = g_off[n], e1 = g_off[n + 1];
        float a0 = 0.f, a1 = 0.f, a2 = 0.f;
        for (int e = e0 + sub; e < e1; e += 8) {
            Edge E = g_edges[e];
            const float* src = h2 + E.s * 3;
            a0 += E.w * src[0];
            a1 += E.w * src[1];
            a2 += E.w * src[2];
        }
        #pragma unroll
        for (int m = 4; m >= 1; m >>= 1) {
            a0 += __shfl_xor_sync(0xFFFFFFFF, a0, m);
            a1 += __shfl_xor_sync(0xFFFFFFFF, a1, m);
            a2 += __shfl_xor_sync(0xFFFFFFFF, a2, m);
        }
        if (sub == 0) {
            hA[n * 3 + 0] = a0;
            hA[n * 3 + 1] = a1;
            hA[n * 3 + 2] = a2;
        }
    }
    __syncthreads();

    for (int n = tid; n < NNODE; n += 1024) {
        #pragma unroll
        for (int sl = 0; sl < SLC; sl++) {
            float g = tanhf(hA[n * 3 + sl] + s_b2[sl]);
            int sb = cta * SLC + sl;
            __nv_bfloat16 hi = __float2bfloat16(g);
            g_ghi[(size_t)sb * K5P + n] = hi;
            g_glo[(size_t)sb * K5P + n] = __float2bfloat16(g - __bfloat162float(hi));
        }
    }
}

// ---------------- gi0 GEMM (unchanged R12 winner) ----------------
#define GSTR 40
#define SA_B (2 * 2 * 64 * GSTR * 2)
#define SB_B (2 * 2 * 128 * GSTR * 2)

__global__ __launch_bounds__(256, 2) void gemm_gi0_kernel() {
    extern __shared__ char smraw[];
    __nv_bfloat16* sA = (__nv_bfloat16*)smraw;
    __nv_bfloat16* sB = (__nv_bfloat16*)(smraw + SA_B);
    unsigned sA_u = smem_u32(sA), sB_u = smem_u32(sB);

    int tid = threadIdx.x;
    int lane = tid & 31, warp = tid >> 5;
    int wm = warp >> 2, wn = warp & 3;
    int m0 = blockIdx.x * 64, n0 = blockIdx.y * 128;
    int c0 = blockIdx.z * KCPS, c1 = c0 + KCPS;

    float d[2][4][4];
    #pragma unroll
    for (int i = 0; i < 2; i++)
        #pragma unroll
        for (int j = 0; j < 4; j++)
            #pragma unroll
            for (int q = 0; q < 4; q++) d[i][j][q] = 0.f;

    int a_hl[2], a_row[2], a_seg[2];
    #pragma unroll
    for (int i = 0; i < 2; i++) {
        int idx = tid + i * 256;
        a_hl[i] = idx >> 8; int r = idx & 255;
        a_row[i] = r >> 2; a_seg[i] = r & 3;
    }
    int b_hl[4], b_row[4], b_seg[4];
    #pragma unroll
    for (int i = 0; i < 4; i++) {
        int idx = tid + i * 256;
        b_hl[i] = idx >> 9; int r = idx & 511;
        b_row[i] = r >> 2; b_seg[i] = r & 3;
    }

    uint4 rA[2], rB[4];
    #pragma unroll
    for (int i = 0; i < 2; i++) {
        const __nv_bfloat16* src = a_hl[i] ? g_glo : g_ghi;
        rA[i] = *(const uint4*)(src + (size_t)(m0 + a_row[i]) * K5P + c0 * 32 + a_seg[i] * 8);
    }
    #pragma unroll
    for (int i = 0; i < 4; i++) {
        const __nv_bfloat16* src = b_hl[i] ? g_wlo : g_whi;
        rB[i] = *(const uint4*)(src + (size_t)(n0 + b_row[i]) * K5P + c0 * 32 + b_seg[i] * 8);
    }
    #pragma unroll
    for (int i = 0; i < 2; i++)
        *(uint4*)(sA + ((a_hl[i]) * 64 + a_row[i]) * GSTR + a_seg[i] * 8) = rA[i];
    #pragma unroll
    for (int i = 0; i < 4; i++)
        *(uint4*)(sB + ((b_hl[i]) * 128 + b_row[i]) * GSTR + b_seg[i] * 8) = rB[i];
    __syncthreads();

    for (int c = c0; c < c1; c++) {
        int buf = (c - c0) & 1;
        if (c + 1 < c1) {
            int kb = (c + 1) * 32;
            #pragma unroll
            for (int i = 0; i < 2; i++) {
                const __nv_bfloat16* src = a_hl[i] ? g_glo : g_ghi;
                rA[i] = *(const uint4*)(src + (size_t)(m0 + a_row[i]) * K5P + kb + a_seg[i] * 8);
            }
            #pragma unroll
            for (int i = 0; i < 4; i++) {
                const __nv_bfloat16* src = b_hl[i] ? g_wlo : g_whi;
                rB[i] = *(const uint4*)(src + (size_t)(n0 + b_row[i]) * K5P + kb + b_seg[i] * 8);
            }
        }
        unsigned aoff = sA_u + buf * (2 * 64 * GSTR * 2);
        unsigned boff = sB_u + buf * (2 * 128 * GSTR * 2);
        #pragma unroll
        for (int kk = 0; kk < 2; kk++) {
            unsigned a[2][2][4], bf[2][4][2];
            int arow = lane & 15;
            int acol = kk * 16 + ((lane >> 4) << 3);
            #pragma unroll
            for (int hl = 0; hl < 2; hl++)
                #pragma unroll
                for (int mi = 0; mi < 2; mi++) {
                    unsigned ad = aoff +
                        ((hl * 64 + wm * 32 + mi * 16 + arow) * GSTR + acol) * 2;
                    ldm_x4(ad, a[hl][mi][0], a[hl][mi][1], a[hl][mi][2], a[hl][mi][3]);
                }
            int bn = (lane & 7) + ((lane >> 4) & 1) * 8;
            int bk = kk * 16 + (lane & 8);
            #pragma unroll
            for (int hl = 0; hl < 2; hl++)
                #pragma unroll
                for (int ni = 0; ni < 2; ni++) {
                    unsigned r0, r1, r2, r3;
                    unsigned ad = boff +
                        ((hl * 128 + wn * 32 + ni * 16 + bn) * GSTR + bk) * 2;
                    ldm_x4(ad, r0, r1, r2, r3);
                    bf[hl][2 * ni][0] = r0;     bf[hl][2 * ni][1] = r1;
                    bf[hl][2 * ni + 1][0] = r2; bf[hl][2 * ni + 1][1] = r3;
                }
            #pragma unroll
            for (int mi = 0; mi < 2; mi++)
                #pragma unroll
                for (int j = 0; j < 4; j++) {
                    mma_bf16(d[mi][j], a[0][mi], bf[0][j]);
                    mma_bf16(d[mi][j], a[0][mi], bf[1][j]);
                    mma_bf16(d[mi][j], a[1][mi], bf[0][j]);
                }
        }
        if (c + 1 < c1) {
            int nb = ((c - c0) & 1) ^ 1;
            #pragma unroll
            for (int i = 0; i < 2; i++)
                *(uint4*)(sA + ((nb * 2 + a_hl[i]) * 64 + a_row[i]) * GSTR + a_seg[i] * 8) = rA[i];
            #pragma unroll
            for (int i = 0; i < 4; i++)
                *(uint4*)(sB + ((nb * 2 + b_hl[i]) * 128 + b_row[i]) * GSTR + b_seg[i] * 8) = rB[i];
        }
        __syncthreads();
    }

    #pragma unroll
    for (int mi = 0; mi < 2; mi++)
        #pragma unroll
        for (int j = 0; j < 4; j++) {
            int row0 = m0 + wm * 32 + mi * 16 + (lane >> 2);
            int col = n0 + wn * 32 + j * 8 + (lane & 3) * 2;
            if (row0 < SB) {
                atomicAdd(&g_gi0[(size_t)row0 * G3 + col], d[mi][j][0]);
                atomicAdd(&g_gi0[(size_t)row0 * G3 + col + 1], d[mi][j][1]);
            }
            if (row0 + 8 < SB) {
                atomicAdd(&g_gi0[(size_t)(row0 + 8) * G3 + col], d[mi][j][2]);
                atomicAdd(&g_gi0[(size_t)(row0 + 8) * G3 + col + 1], d[mi][j][3]);
            }
        }
}

// ---------------- persistent GRU: 512 threads, 4 batches/thread ----------------
#define KSEG 144          // 128 data + 16 hole (ull offset 72 = 8 mod 16)
#define HPX  578          // 4*KSEG + 2   (ull stride 289 = 1 mod 16)
#define WPS  580
#define GRU_SMEM ((48 * WPS + 32 * HPX) * 4)

__global__ __launch_bounds__(512, 1) void gru_persist_kernel(
        const float* __restrict__ whh0, const float* __restrict__ bhh0,
        const float* __restrict__ wih1, const float* __restrict__ bih1,
        const float* __restrict__ whh1, const float* __restrict__ bhh1,
        float* __restrict__ d_out) {
    extern __shared__ float sm[];
    float* s_w = sm;
    float* s_h = sm + 48 * WPS;
    int tid = threadIdx.x;
    int role = blockIdx.x >> 5;
    int c = blockIdx.x & 31;

    const float* wsrc = (role == 0) ? whh0 : ((role == 1) ? wih1 : whh1);
    for (int e = tid; e < 48 * 512; e += 512) {
        int r = e >> 9, k = e & 511;
        int G = (role == 1) ? (c * 48 + r) : ((r >> 4) * HID + c * 16 + (r & 15));
        s_w[r * WPS + (k >> 7) * KSEG + (k & 127)] = wsrc[(size_t)G * HID + k];
    }

    int jl = tid >> 5, lane = tid & 31;
    int ks = lane >> 3, bg = lane & 7;
    const ull* wp0 = (const ull*)(s_w + (0 * 16 + jl) * WPS + ks * KSEG);
    const ull* wp1 = (const ull*)(s_w + (1 * 16 + jl) * WPS + ks * KSEG);
    const ull* wp2 = (const ull*)(s_w + (2 * 16 + jl) * WPS + ks * KSEG);
    const ull* hp[4];
    #pragma unroll
    for (int i = 0; i < 4; i++)
        hp[i] = (const ull*)(s_h + (bg + 8 * i) * HPX + ks * KSEG);

    for (int t = 0; t < S; t++) {
        if (tid == 0) {
            if (role == 0) { if (t) spin32(&g_f0[t - 1]); }
            else if (role == 1) { spin32(&g_f0[t]); }
            else { spin32(&g_f1[t]); if (t) spin32(&g_f2[t - 1]); }
        }
        __syncthreads();

        const float* hsrc = (role == 0) ? (g_h0s + (size_t)t * BH)
                          : (role == 1) ? (g_h0s + (size_t)(t + 1) * BH)
                                        : (g_h1s + (size_t)t * BH);
        for (int e = tid; e < 32 * 128; e += 512) {
            int b = e >> 7, k4 = (e & 127) * 4;
            float4 v = *(const float4*)(hsrc + (size_t)b * HID + k4);
            float* dst = s_h + b * HPX + (k4 >> 7) * KSEG + (k4 & 127);
            *(float2*)dst = make_float2(v.x, v.y);
            *(float2*)(dst + 2) = make_float2(v.z, v.w);
        }
        __syncthreads();

        ull a0[4], a1[4], a2[4];
        #pragma unroll
        for (int i = 0; i < 4; i++) { a0[i] = 0ull; a1[i] = 0ull; a2[i] = 0ull; }

        #pragma unroll 4
        for (int q = 0; q < 64; q++) {
            ull v0 = wp0[q], v1 = wp1[q], v2 = wp2[q];
            #pragma unroll
            for (int i = 0; i < 4; i++) {
                ull h = hp[i][q];
                FFMA2(a0[i], h, v0);
                FFMA2(a1[i], h, v1);
                FFMA2(a2[i], h, v2);
            }
        }

        // full k reduction across ks groups (lane bits 3-4)
        float sv0[4], sv1[4], sv2[4];
        #pragma unroll
        for (int i = 0; i < 4; i++) {
            float v;
            v = hsum2(a0[i]);
            v += __shfl_xor_sync(0xFFFFFFFF, v, 8);
            v += __shfl_xor_sync(0xFFFFFFFF, v, 16);
            sv0[i] = v;
            v = hsum2(a1[i]);
            v += __shfl_xor_sync(0xFFFFFFFF, v, 8);
            v += __shfl_xor_sync(0xFFFFFFFF, v, 16);
            sv1[i] = v;
            v = hsum2(a2[i]);
            v += __shfl_xor_sync(0xFFFFFFFF, v, 8);
            v += __shfl_xor_sync(0xFFFFFFFF, v, 16);
            sv2[i] = v;
        }

        int b = bg + 8 * ks;   // this thread finalizes batch b (i = ks)
        if (role == 1) {
            float* gi = g_gi1 + (size_t)t * BATCH * G3;
            int r0 = c * 48 + jl, r1 = r0 + 16, r2 = r0 + 32;
            gi[(size_t)b * G3 + r0] = sv0[ks] + bih1[r0];
            gi[(size_t)b * G3 + r1] = sv1[ks] + bih1[r1];
            gi[(size_t)b * G3 + r2] = sv2[ks] + bih1[r2];
        } else {
            int j = c * 16 + jl;
            const float* bhh = (role == 0) ? bhh0 : bhh1;
            const float* gi = ((role == 0) ? g_gi0 : g_gi1) + (size_t)t * BATCH * G3;
            float* hdst = ((role == 0) ? g_h0s : g_h1s) + (size_t)(t + 1) * BH;
            int joff = (j >> 7) * KSEG + (j & 127);
            float ghr = sv0[ks] + bhh[j];
            float ghz = sv1[ks] + bhh[HID + j];
            float ghn = sv2[ks] + bhh[2 * HID + j];
            float gir = gi[(size_t)b * G3 + j];
            float giz = gi[(size_t)b * G3 + HID + j];
            float gin = gi[(size_t)b * G3 + 2 * HID + j];
            float r = 1.f / (1.f + expf(-(gir + ghr)));
            float z = 1.f / (1.f + expf(-(giz + ghz)));
            float n = tanhf(gin + r * ghn);
            float hprev = s_h[b * HPX + joff];
            float hnew = (1.f - z) * n + z * hprev;
            hdst[(size_t)b * HID + j] = hnew;
            if (role == 2) d_out[(size_t)t * BH + b * HID + j] = hnew;
            if (t == S - 1)
                d_out[(size_t)S * BH + (role == 2 ? BH : 0) + b * HID + j] = hnew;
        }

        __syncthreads();
        if (tid == 0) {
            int* f = (role == 0) ? &g_f0[t] : ((role == 1) ? &g_f1[t] : &g_f2[t]);
            red_release(f);
        }
    }
}

// ---------------- host launch ----------------
extern "C" void kernel_launch(void* const* d_in, const int* in_sizes, int n_in,
                              void* d_out, int out_size) {
    const float* x     = (const float*)d_in[0];
    const int*   ei    = (const int*)d_in[1];
    const float* W1    = (const float*)d_in[2];
    const float* b1    = (const float*)d_in[3];
    const float* W2    = (const float*)d_in[4];
    const float* b2    = (const float*)d_in[5];
    const float* w_ih0 = (const float*)d_in[6];
    const float* w_hh0 = (const float*)d_in[7];
    const float* b_ih0 = (const float*)d_in[8];
    const float* b_hh0 = (const float*)d_in[9];
    const float* w_ih1 = (const float*)d_in[10];
    const float* w_hh1 = (const float*)d_in[11];
    const float* b_ih1 = (const float*)d_in[12];
    const float* b_hh1 = (const float*)d_in[13];
    float* out = (float*)d_out;

    const int SMEM_GEMM = SA_B + SB_B;

    cudaFuncSetAttribute(gcn_kernel, cudaFuncAttributeMaxDynamicSharedMemorySize, SMEM_GCN);
    cudaFuncSetAttribute(gemm_gi0_kernel, cudaFuncAttributeMaxDynamicSharedMemorySize, SMEM_GEMM);
    cudaFuncSetAttribute(gru_persist_kernel, cudaFuncAttributeMaxDynamicSharedMemorySize, GRU_SMEM);

    prep_kernel<<<PREP_CTAS, 256>>>(ei);
    gcn_kernel<<<GCN_CTAS + WCONV_CTAS, 1024, SMEM_GCN>>>(x, W1, b1, W2, b2, w_ih0, b_ih0);
    gemm_gi0_kernel<<<dim3(MP / 64, G3 / 128, KSPL), 256, SMEM_GEMM>>>();
    gru_persist_kernel<<<96, 512, GRU_SMEM>>>(w_hh0, b_hh0, w_ih1, b_ih1,
                                              w_hh1, b_hh1, out);   // capture slot #4
}

// round 15
// speedup vs baseline: 1.1277x; 1.1277x over previous
#include <cuda_runtime.h>
#include <cuda_bf16.h>
#include <math.h>

#define S      15
#define BATCH  32
#define NNODE  5000
#define NEDGE  80000
#define NEDGE_SL (NEDGE + NNODE)
#define FIN    16
#define HID    512
#define G3     1536
#define SB     (S*BATCH)
#define K5     5000
#define K5P    5088
#define MP     512
#define KCH    159
#define KSPL   3
#define KCPS   53
#define BH     (BATCH*HID)
#define SLC    3
#define GCN_CTAS (SB / SLC)
#define WCONV_CTAS 40
#define PREP_CTAS 313

typedef unsigned long long ull;

struct __align__(8) Edge { int s; float w; };

__device__ int   g_indeg[NNODE];
__device__ int   g_off[NNODE + 1];
__device__ int   g_pos[NNODE];
__device__ float g_dinv[NNODE];
__device__ Edge  g_edges[NEDGE_SL];
__device__ int   g_is64;
__device__ int   g_syncA, g_syncB, g_syncC;

__device__ __nv_bfloat16 g_ghi[MP * K5P];
__device__ __nv_bfloat16 g_glo[MP * K5P];
__device__ __nv_bfloat16 g_whi[G3 * K5P];
__device__ __nv_bfloat16 g_wlo[G3 * K5P];

__device__ float g_gi0[SB * G3];
__device__ float g_gi1[S * BATCH * G3];
__device__ float g_h0s[(S + 1) * BH];
__device__ float g_h1s[(S + 1) * BH];
__device__ int   g_f0[S], g_f1[S], g_f2[S];

__device__ __forceinline__ unsigned smem_u32(const void* p) {
    return (unsigned)__cvta_generic_to_shared(p);
}
__device__ __forceinline__ void ldm_x4(unsigned a, unsigned& r0, unsigned& r1,
                                       unsigned& r2, unsigned& r3) {
    asm volatile("ldmatrix.sync.aligned.m8n8.x4.shared.b16 {%0,%1,%2,%3}, [%4];"
                 : "=r"(r0), "=r"(r1), "=r"(r2), "=r"(r3) : "r"(a));
}
__device__ __forceinline__ void mma_bf16(float* d, const unsigned* a, const unsigned* b) {
    asm volatile(
        "mma.sync.aligned.m16n8k16.row.col.f32.bf16.bf16.f32 "
        "{%0,%1,%2,%3}, {%4,%5,%6,%7}, {%8,%9}, {%0,%1,%2,%3};"
        : "+f"(d[0]), "+f"(d[1]), "+f"(d[2]), "+f"(d[3])
        : "r"(a[0]), "r"(a[1]), "r"(a[2]), "r"(a[3]), "r"(b[0]), "r"(b[1]));
}
__device__ __forceinline__ void spin_ge(const int* p, int n) {
    int v;
    do {
        asm volatile("ld.acquire.gpu.b32 %0, [%1];" : "=r"(v) : "l"(p));
        if (v < n) __nanosleep(32);
    } while (v < n);
}
__device__ __forceinline__ void spin32(const int* p) { spin_ge(p, 32); }
__device__ __forceinline__ void red_release(int* p) {
    asm volatile("red.release.gpu.global.add.s32 [%0], %1;" :: "l"(p), "r"(1) : "memory");
}

// ---------------- merged prep (unchanged) ----------------
__global__ __launch_bounds__(256) void prep_kernel(const int* __restrict__ ei) {
    int tid = threadIdx.x;
    int gid = blockIdx.x * 256 + tid;

    if (gid == 0) {
        int f = 1;
        for (int q = 0; q < 64; q++) if (ei[2 * q + 1] != 0) { f = 0; break; }
        g_is64 = f;
    }
    if (gid < NNODE) g_indeg[gid] = 1;
    if (gid < BH) { g_h0s[gid] = 0.f; g_h1s[gid] = 0.f; }
    if (gid < S) { g_f0[gid] = 0; g_f1[gid] = 0; g_f2[gid] = 0; }
    __syncthreads();
    if (tid == 0) { red_release(&g_syncA); spin_ge(&g_syncA, PREP_CTAS); }
    __syncthreads();

    if (gid < NEDGE) {
        int t = g_is64 ? ei[2 * (NEDGE + gid)] : ei[NEDGE + gid];
        atomicAdd(&g_indeg[t], 1);
    }
    __syncthreads();
    if (tid == 0) { red_release(&g_syncB); spin_ge(&g_syncB, PREP_CTAS); }
    __syncthreads();

    if (blockIdx.x == 0) {
        __shared__ int ssum[256];
        int vals[20]; int s = 0;
        #pragma unroll
        for (int q = 0; q < 20; q++) {
            int idx = tid * 20 + q;
            vals[q] = (idx < NNODE) ? g_indeg[idx] : 0;
            s += vals[q];
        }
        ssum[tid] = s;
        __syncthreads();
        for (int off = 1; off < 256; off <<= 1) {
            int v = (tid >= off) ? ssum[tid - off] : 0;
            __syncthreads();
            ssum[tid] += v;
            __syncthreads();
        }
        int run = ssum[tid] - s;
        #pragma unroll
        for (int q = 0; q < 20; q++) {
            int idx = tid * 20 + q;
            if (idx < NNODE) {
                g_off[idx] = run; g_pos[idx] = run;
                g_dinv[idx] = rsqrtf((float)vals[q]);
                run += vals[q];
            }
        }
        if (tid == 255) g_off[NNODE] = ssum[255];
        __syncthreads();
        if (tid == 0) red_release(&g_syncC);
    }
    if (tid == 0) spin_ge(&g_syncC, 1);
    __syncthreads();

    for (int e = gid; e < NEDGE_SL; e += PREP_CTAS * 256) {
        int is64 = g_is64;
        int s, t;
        if (e < NEDGE) {
            s = is64 ? ei[2 * e] : ei[e];
            t = is64 ? ei[2 * (NEDGE + e)] : ei[NEDGE + e];
        } else { s = t = e - NEDGE; }
        int idx = atomicAdd(&g_pos[t], 1);
        Edge E; E.s = s; E.w = g_dinv[s] * g_dinv[t];
        g_edges[idx] = E;
    }
}

// ---------------- fused GCN + wconv + gi0 bias prefill (unchanged) ----------------
#define SMEM_GCN ((NNODE * 6 + NNODE * 3) * 4)

__global__ __launch_bounds__(1024) void gcn_kernel(const float* __restrict__ x,
                                                   const float* __restrict__ W1,
                                                   const float* __restrict__ b1,
                                                   const float* __restrict__ W2,
                                                   const float* __restrict__ b2,
                                                   const float* __restrict__ wih0,
                                                   const float* __restrict__ bih0) {
    int cta = blockIdx.x, tid = threadIdx.x;

    if (cta >= GCN_CTAS) {
        if (cta == GCN_CTAS && tid == 0) {
            g_syncA = 0; g_syncB = 0; g_syncC = 0;
        }
        int base = (cta - GCN_CTAS) * 1024 + tid;
        for (int i = base; i < G3 * K5; i += WCONV_CTAS * 1024) {
            int n = i / K5, k = i - n * K5;
            float v = wih0[i];
            __nv_bfloat16 hi = __float2bfloat16(v);
            g_whi[(size_t)n * K5P + k] = hi;
            g_wlo[(size_t)n * K5P + k] = __float2bfloat16(v - __bfloat162float(hi));
        }
        for (int i = base; i < SB * G3; i += WCONV_CTAS * 1024)
            g_gi0[i] = bih0[i % G3];
        return;
    }

    extern __shared__ float sm[];
    float* hA = sm;
    float* h2 = sm + NNODE * 6;
    __shared__ float s_w1[SLC][FIN][2];
    __shared__ float s_b1[SLC][2], s_w2[SLC][2], s_b2[SLC];

    if (tid < SLC * FIN * 2) {
        int sl = tid / (FIN * 2), rem = tid % (FIN * 2);
        int s = (cta * SLC + sl) >> 5;
        s_w1[sl][rem >> 1][rem & 1] = W1[s * (FIN * 2) + rem];
    }
    if (tid >= 128 && tid < 128 + SLC * 2) {
        int q = tid - 128; int sl = q >> 1, c = q & 1;
        int s = (cta * SLC + sl) >> 5;
        s_b1[sl][c] = b1[s * 2 + c];
        s_w2[sl][c] = W2[s * 2 + c];
    }
    if (tid >= 160 && tid < 160 + SLC) {
        int sl = tid - 160;
        s_b2[sl] = b2[((cta * SLC + sl) >> 5)];
    }
    __syncthreads();

    for (int idx = tid; idx < SLC * NNODE; idx += 1024) {
        int sl = idx / NNODE, n = idx - sl * NNODE;
        const float4* xp = (const float4*)(x + ((size_t)(cta * SLC + sl) * NNODE + n) * FIN);
        float xv[16];
        *(float4*)&xv[0] = xp[0]; *(float4*)&xv[4] = xp[1];
        *(float4*)&xv[8] = xp[2]; *(float4*)&xv[12] = xp[3];
        float a0 = 0.f, a1 = 0.f;
        #pragma unroll
        for (int f = 0; f < FIN; f++) {
            a0 += xv[f] * s_w1[sl][f][0];
            a1 += xv[f] * s_w1[sl][f][1];
        }
        hA[n * 6 + sl * 2]     = a0;
        hA[n * 6 + sl * 2 + 1] = a1;
    }
    __syncthreads();

    int warp = tid >> 5, lane = tid & 31;
    int seg = lane >> 3, sub = lane & 7;

    for (int n0 = warp * 4; n0 < NNODE; n0 += 128) {
        int n = n0 + seg;
        int e0 = g_off[n], e1 = g_off[n + 1];
        float ac0 = 0.f, ac1 = 0.f, ac2 = 0.f, ac3 = 0.f, ac4 = 0.f, ac5 = 0.f;
        for (int e = e0 + sub; e < e1; e += 8) {
            Edge E = g_edges[e];
            const float2* src = (const float2*)(hA + E.s * 6);
            float2 p0 = src[0], p1 = src[1], p2 = src[2];
            ac0 += E.w * p0.x; ac1 += E.w * p0.y;
            ac2 += E.w * p1.x; ac3 += E.w * p1.y;
            ac4 += E.w * p2.x; ac5 += E.w * p2.y;
        }
        #pragma unroll
        for (int m = 4; m >= 1; m >>= 1) {
            ac0 += __shfl_xor_sync(0xFFFFFFFF, ac0, m);
            ac1 += __shfl_xor_sync(0xFFFFFFFF, ac1, m);
            ac2 += __shfl_xor_sync(0xFFFFFFFF, ac2, m);
            ac3 += __shfl_xor_sync(0xFFFFFFFF, ac3, m);
            ac4 += __shfl_xor_sync(0xFFFFFFFF, ac4, m);
            ac5 += __shfl_xor_sync(0xFFFFFFFF, ac5, m);
        }
        if (sub == 0) {
            float r0, r1;
            r0 = fmaxf(ac0 + s_b1[0][0], 0.f); r1 = fmaxf(ac1 + s_b1[0][1], 0.f);
            h2[n * 3 + 0] = r0 * s_w2[0][0] + r1 * s_w2[0][1];
            r0 = fmaxf(ac2 + s_b1[1][0], 0.f); r1 = fmaxf(ac3 + s_b1[1][1], 0.f);
            h2[n * 3 + 1] = r0 * s_w2[1][0] + r1 * s_w2[1][1];
            r0 = fmaxf(ac4 + s_b1[2][0], 0.f); r1 = fmaxf(ac5 + s_b1[2][1], 0.f);
            h2[n * 3 + 2] = r0 * s_w2[2][0] + r1 * s_w2[2][1];
        }
    }
    __syncthreads();

    for (int n0 = warp * 4; n0 < NNODE; n0 += 128) {
        int n = n0 + seg;
        int e0 = g_off[n], e1 = g_off[n + 1];
        float a0 = 0.f, a1 = 0.f, a2 = 0.f;
        for (int e = e0 + sub; e < e1; e += 8) {
            Edge E = g_edges[e];
            const float* src = h2 + E.s * 3;
            a0 += E.w * src[0];
            a1 += E.w * src[1];
            a2 += E.w * src[2];
        }
        #pragma unroll
        for (int m = 4; m >= 1; m >>= 1) {
            a0 += __shfl_xor_sync(0xFFFFFFFF, a0, m);
            a1 += __shfl_xor_sync(0xFFFFFFFF, a1, m);
            a2 += __shfl_xor_sync(0xFFFFFFFF, a2, m);
        }
        if (sub == 0) {
            hA[n * 3 + 0] = a0;
            hA[n * 3 + 1] = a1;
            hA[n * 3 + 2] = a2;
        }
    }
    __syncthreads();

    for (int n = tid; n < NNODE; n += 1024) {
        #pragma unroll
        for (int sl = 0; sl < SLC; sl++) {
            float g = tanhf(hA[n * 3 + sl] + s_b2[sl]);
            int sb = cta * SLC + sl;
            __nv_bfloat16 hi = __float2bfloat16(g);
            g_ghi[(size_t)sb * K5P + n] = hi;
            g_glo[(size_t)sb * K5P + n] = __float2bfloat16(g - __bfloat162float(hi));
        }
    }
}

// ---------------- gi0 GEMM (unchanged R12 winner) ----------------
#define GSTR 40
#define SA_B (2 * 2 * 64 * GSTR * 2)
#define SB_B (2 * 2 * 128 * GSTR * 2)

__global__ __launch_bounds__(256, 2) void gemm_gi0_kernel() {
    extern __shared__ char smraw[];
    __nv_bfloat16* sA = (__nv_bfloat16*)smraw;
    __nv_bfloat16* sB = (__nv_bfloat16*)(smraw + SA_B);
    unsigned sA_u = smem_u32(sA), sB_u = smem_u32(sB);

    int tid = threadIdx.x;
    int lane = tid & 31, warp = tid >> 5;
    int wm = warp >> 2, wn = warp & 3;
    int m0 = blockIdx.x * 64, n0 = blockIdx.y * 128;
    int c0 = blockIdx.z * KCPS, c1 = c0 + KCPS;

    float d[2][4][4];
    #pragma unroll
    for (int i = 0; i < 2; i++)
        #pragma unroll
        for (int j = 0; j < 4; j++)
            #pragma unroll
            for (int q = 0; q < 4; q++) d[i][j][q] = 0.f;

    int a_hl[2], a_row[2], a_seg[2];
    #pragma unroll
    for (int i = 0; i < 2; i++) {
        int idx = tid + i * 256;
        a_hl[i] = idx >> 8; int r = idx & 255;
        a_row[i] = r >> 2; a_seg[i] = r & 3;
    }
    int b_hl[4], b_row[4], b_seg[4];
    #pragma unroll
    for (int i = 0; i < 4; i++) {
        int idx = tid + i * 256;
        b_hl[i] = idx >> 9; int r = idx & 511;
        b_row[i] = r >> 2; b_seg[i] = r & 3;
    }

    uint4 rA[2], rB[4];
    #pragma unroll
    for (int i = 0; i < 2; i++) {
        const __nv_bfloat16* src = a_hl[i] ? g_glo : g_ghi;
        rA[i] = *(const uint4*)(src + (size_t)(m0 + a_row[i]) * K5P + c0 * 32 + a_seg[i] * 8);
    }
    #pragma unroll
    for (int i = 0; i < 4; i++) {
        const __nv_bfloat16* src = b_hl[i] ? g_wlo : g_whi;
        rB[i] = *(const uint4*)(src + (size_t)(n0 + b_row[i]) * K5P + c0 * 32 + b_seg[i] * 8);
    }
    #pragma unroll
    for (int i = 0; i < 2; i++)
        *(uint4*)(sA + ((a_hl[i]) * 64 + a_row[i]) * GSTR + a_seg[i] * 8) = rA[i];
    #pragma unroll
    for (int i = 0; i < 4; i++)
        *(uint4*)(sB + ((b_hl[i]) * 128 + b_row[i]) * GSTR + b_seg[i] * 8) = rB[i];
    __syncthreads();

    for (int c = c0; c < c1; c++) {
        int buf = (c - c0) & 1;
        if (c + 1 < c1) {
            int kb = (c + 1) * 32;
            #pragma unroll
            for (int i = 0; i < 2; i++) {
                const __nv_bfloat16* src = a_hl[i] ? g_glo : g_ghi;
                rA[i] = *(const uint4*)(src + (size_t)(m0 + a_row[i]) * K5P + kb + a_seg[i] * 8);
            }
            #pragma unroll
            for (int i = 0; i < 4; i++) {
                const __nv_bfloat16* src = b_hl[i] ? g_wlo : g_whi;
                rB[i] = *(const uint4*)(src + (size_t)(n0 + b_row[i]) * K5P + kb + b_seg[i] * 8);
            }
        }
        unsigned aoff = sA_u + buf * (2 * 64 * GSTR * 2);
        unsigned boff = sB_u + buf * (2 * 128 * GSTR * 2);
        #pragma unroll
        for (int kk = 0; kk < 2; kk++) {
            unsigned a[2][2][4], bf[2][4][2];
            int arow = lane & 15;
            int acol = kk * 16 + ((lane >> 4) << 3);
            #pragma unroll
            for (int hl = 0; hl < 2; hl++)
                #pragma unroll
                for (int mi = 0; mi < 2; mi++) {
                    unsigned ad = aoff +
                        ((hl * 64 + wm * 32 + mi * 16 + arow) * GSTR + acol) * 2;
                    ldm_x4(ad, a[hl][mi][0], a[hl][mi][1], a[hl][mi][2], a[hl][mi][3]);
                }
            int bn = (lane & 7) + ((lane >> 4) & 1) * 8;
            int bk = kk * 16 + (lane & 8);
            #pragma unroll
            for (int hl = 0; hl < 2; hl++)
                #pragma unroll
                for (int ni = 0; ni < 2; ni++) {
                    unsigned r0, r1, r2, r3;
                    unsigned ad = boff +
                        ((hl * 128 + wn * 32 + ni * 16 + bn) * GSTR + bk) * 2;
                    ldm_x4(ad, r0, r1, r2, r3);
                    bf[hl][2 * ni][0] = r0;     bf[hl][2 * ni][1] = r1;
                    bf[hl][2 * ni + 1][0] = r2; bf[hl][2 * ni + 1][1] = r3;
                }
            #pragma unroll
            for (int mi = 0; mi < 2; mi++)
                #pragma unroll
                for (int j = 0; j < 4; j++) {
                    mma_bf16(d[mi][j], a[0][mi], bf[0][j]);
                    mma_bf16(d[mi][j], a[0][mi], bf[1][j]);
                    mma_bf16(d[mi][j], a[1][mi], bf[0][j]);
                }
        }
        if (c + 1 < c1) {
            int nb = ((c - c0) & 1) ^ 1;
            #pragma unroll
            for (int i = 0; i < 2; i++)
                *(uint4*)(sA + ((nb * 2 + a_hl[i]) * 64 + a_row[i]) * GSTR + a_seg[i] * 8) = rA[i];
            #pragma unroll
            for (int i = 0; i < 4; i++)
                *(uint4*)(sB + ((nb * 2 + b_hl[i]) * 128 + b_row[i]) * GSTR + b_seg[i] * 8) = rB[i];
        }
        __syncthreads();
    }

    #pragma unroll
    for (int mi = 0; mi < 2; mi++)
        #pragma unroll
        for (int j = 0; j < 4; j++) {
            int row0 = m0 + wm * 32 + mi * 16 + (lane >> 2);
            int col = n0 + wn * 32 + j * 8 + (lane & 3) * 2;
            if (row0 < SB) {
                atomicAdd(&g_gi0[(size_t)row0 * G3 + col], d[mi][j][0]);
                atomicAdd(&g_gi0[(size_t)row0 * G3 + col + 1], d[mi][j][1]);
            }
            if (row0 + 8 < SB) {
                atomicAdd(&g_gi0[(size_t)(row0 + 8) * G3 + col], d[mi][j][2]);
                atomicAdd(&g_gi0[(size_t)(row0 + 8) * G3 + col + 1], d[mi][j][3]);
            }
        }
}

// ---------------- persistent GRU: mma.sync h-GEMM ----------------
// smem: s_w bf16[2][48][HSTR] | s_hb bf16[2][32][HSTR] | s_part f32[3][32][17] | s_gh f32[48*33]
#define HSTR 520
#define SW_BYTES (2 * 48 * HSTR * 2)        // 99840
#define SH_BYTES (2 * 32 * HSTR * 2)        // 66560
#define SPART_OFF (SW_BYTES + SH_BYTES)     // 166400
#define SGH_OFF (SPART_OFF + 3 * 32 * 17 * 4)  // 172928
#define GRU_SMEM (SGH_OFF + 48 * 33 * 4)    // 179264

__global__ __launch_bounds__(256, 1) void gru_persist_kernel(
        const float* __restrict__ whh0, const float* __restrict__ bhh0,
        const float* __restrict__ wih1, const float* __restrict__ bih1,
        const float* __restrict__ whh1, const float* __restrict__ bhh1,
        float* __restrict__ d_out) {
    extern __shared__ char smr[];
    __nv_bfloat16* s_w  = (__nv_bfloat16*)smr;
    __nv_bfloat16* s_hb = (__nv_bfloat16*)(smr + SW_BYTES);
    float* s_part = (float*)(smr + SPART_OFF);
    float* s_gh   = (float*)(smr + SGH_OFF);
    unsigned sw_u = smem_u32(s_w), shb_u = smem_u32(s_hb);

    int tid = threadIdx.x;
    int warp = tid >> 5, lane = tid & 31;
    int role = blockIdx.x >> 5;
    int c = blockIdx.x & 31;

    // one-time weight split into bf16 hi/lo
    const float* wsrc = (role == 0) ? whh0 : ((role == 1) ? wih1 : whh1);
    for (int e = tid; e < 48 * 512; e += 256) {
        int ni = e >> 9, k = e & 511;
        int G = (role == 1) ? (c * 48 + ni) : ((ni >> 4) * HID + c * 16 + (ni & 15));
        float v = wsrc[(size_t)G * HID + k];
        __nv_bfloat16 hi = __float2bfloat16(v);
        s_w[(0 * 48 + ni) * HSTR + k] = hi;
        s_w[(1 * 48 + ni) * HSTR + k] = __float2bfloat16(v - __bfloat162float(hi));
    }

    int ng = warp >> 1, kh = warp & 1;

    for (int t = 0; t < S; t++) {
        if (tid == 0) {
            if (role == 0) { if (t) spin32(&g_f0[t - 1]); }
            else if (role == 1) { spin32(&g_f0[t]); }
            else { spin32(&g_f1[t]); if (t) spin32(&g_f2[t - 1]); }
        }
        __syncthreads();

        const float* hsrc = (role == 0) ? (g_h0s + (size_t)t * BH)
                          : (role == 1) ? (g_h0s + (size_t)(t + 1) * BH)
                                        : (g_h1s + (size_t)t * BH);
        // stage h -> bf16 hi/lo
        for (int e = tid; e < 32 * 128; e += 256) {
            int b = e >> 7, kq = (e & 127) * 4;
            float4 v = *(const float4*)(hsrc + (size_t)b * HID + kq);
            __nv_bfloat16 h0 = __float2bfloat16(v.x), h1 = __float2bfloat16(v.y);
            __nv_bfloat16 h2 = __float2bfloat16(v.z), h3 = __float2bfloat16(v.w);
            __nv_bfloat16 l0 = __float2bfloat16(v.x - __bfloat162float(h0));
            __nv_bfloat16 l1 = __float2bfloat16(v.y - __bfloat162float(h1));
            __nv_bfloat16 l2 = __float2bfloat16(v.z - __bfloat162float(h2));
            __nv_bfloat16 l3 = __float2bfloat16(v.w - __bfloat162float(h3));
            __nv_bfloat162* dh = (__nv_bfloat162*)(s_hb + (0 * 32 + b) * HSTR + kq);
            dh[0] = __nv_bfloat162(h0, h1);
            dh[1] = __nv_bfloat162(h2, h3);
            __nv_bfloat162* dl = (__nv_bfloat162*)(s_hb + (1 * 32 + b) * HSTR + kq);
            dl[0] = __nv_bfloat162(l0, l1);
            dl[1] = __nv_bfloat162(l2, l3);
        }
        __syncthreads();

        float d[2][2][4];
        #pragma unroll
        for (int mi = 0; mi < 2; mi++)
            #pragma unroll
            for (int nj = 0; nj < 2; nj++)
                #pragma unroll
                for (int q = 0; q < 4; q++) d[mi][nj][q] = 0.f;

        if (warp < 6) {
            int arow = lane & 15, acolo = (lane >> 4) << 3;
            int bn = (lane & 7) + ((lane >> 4) & 1) * 8;
            int bko = lane & 8;
            for (int kc = kh * 16; kc < kh * 16 + 16; kc++) {
                int k0 = kc * 16;
                unsigned a[2][2][4], bfr[2][2][2];
                #pragma unroll
                for (int hl = 0; hl < 2; hl++)
                    #pragma unroll
                    for (int mi = 0; mi < 2; mi++) {
                        unsigned ad = shb_u +
                            ((hl * 32 + mi * 16 + arow) * HSTR + k0 + acolo) * 2;
                        ldm_x4(ad, a[hl][mi][0], a[hl][mi][1], a[hl][mi][2], a[hl][mi][3]);
                    }
                #pragma unroll
                for (int hl = 0; hl < 2; hl++) {
                    unsigned r0, r1, r2, r3;
                    unsigned ad = sw_u +
                        ((hl * 48 + ng * 16 + bn) * HSTR + k0 + bko) * 2;
                    ldm_x4(ad, r0, r1, r2, r3);
                    bfr[hl][0][0] = r0; bfr[hl][0][1] = r1;
                    bfr[hl][1][0] = r2; bfr[hl][1][1] = r3;
                }
                #pragma unroll
                for (int mi = 0; mi < 2; mi++)
                    #pragma unroll
                    for (int nj = 0; nj < 2; nj++) {
                        mma_bf16(d[mi][nj], a[0][mi], bfr[0][nj]);
                        mma_bf16(d[mi][nj], a[0][mi], bfr[1][nj]);
                        mma_bf16(d[mi][nj], a[1][mi], bfr[0][nj]);
                    }
            }
            if (kh == 1) {
                #pragma unroll
                for (int mi = 0; mi < 2; mi++)
                    #pragma unroll
                    for (int nj = 0; nj < 2; nj++)
                        #pragma unroll
                        for (int q = 0; q < 4; q++) {
                            int m = mi * 16 + (lane >> 2) + ((q >> 1) << 3);
                            int ncl = nj * 8 + (lane & 3) * 2 + (q & 1);
                            s_part[(ng * 32 + m) * 17 + ncl] = d[mi][nj][q];
                        }
            }
        }
        __syncthreads();
        if (warp < 6 && kh == 0) {
            #pragma unroll
            for (int mi = 0; mi < 2; mi++)
                #pragma unroll
                for (int nj = 0; nj < 2; nj++)
                    #pragma unroll
                    for (int q = 0; q < 4; q++) {
                        int m = mi * 16 + (lane >> 2) + ((q >> 1) << 3);
                        int ncl = nj * 8 + (lane & 3) * 2 + (q & 1);
                        float v = d[mi][nj][q] + s_part[(ng * 32 + m) * 17 + ncl];
                        s_gh[(ng * 16 + ncl) * 33 + m] = v;
                    }
        }
        __syncthreads();

        if (role == 1) {
            float* gi = g_gi1 + (size_t)t * BATCH * G3;
            for (int e = tid; e < 1536; e += 256) {
                int b = e / 48, ni = e - b * 48;
                gi[(size_t)b * G3 + c * 48 + ni] = s_gh[ni * 33 + b] + bih1[c * 48 + ni];
            }
        } else {
            const float* bhh = (role == 0) ? bhh0 : bhh1;
            const float* gi = ((role == 0) ? g_gi0 : g_gi1) + (size_t)t * BATCH * G3;
            float* hdst = ((role == 0) ? g_h0s : g_h1s) + (size_t)(t + 1) * BH;
            for (int e = tid; e < 512; e += 256) {
                int b = e >> 4, jj = e & 15;
                int j = c * 16 + jj;
                float ghr = s_gh[(0 * 16 + jj) * 33 + b] + bhh[j];
                float ghz = s_gh[(1 * 16 + jj) * 33 + b] + bhh[HID + j];
                float ghn = s_gh[(2 * 16 + jj) * 33 + b] + bhh[2 * HID + j];
                float gir = gi[(size_t)b * G3 + j];
                float giz = gi[(size_t)b * G3 + HID + j];
                float gin = gi[(size_t)b * G3 + 2 * HID + j];
                float r = 1.f / (1.f + expf(-(gir + ghr)));
                float z = 1.f / (1.f + expf(-(giz + ghz)));
                float n = tanhf(gin + r * ghn);
                float hprev = hsrc[(size_t)b * HID + j];
                float hnew = (1.f - z) * n + z * hprev;
                hdst[(size_t)b * HID + j] = hnew;
                if (role == 2) d_out[(size_t)t * BH + b * HID + j] = hnew;
                if (t == S - 1)
                    d_out[(size_t)S * BH + (role == 2 ? BH : 0) + b * HID + j] = hnew;
            }
        }

        __syncthreads();
        if (tid == 0) {
            int* f = (role == 0) ? &g_f0[t] : ((role == 1) ? &g_f1[t] : &g_f2[t]);
            red_release(f);
        }
    }
}

// ---------------- host launch ----------------
extern "C" void kernel_launch(void* const* d_in, const int* in_sizes, int n_in,
                              void* d_out, int out_size) {
    const float* x     = (const float*)d_in[0];
    const int*   ei    = (const int*)d_in[1];
    const float* W1    = (const float*)d_in[2];
    const float* b1    = (const float*)d_in[3];
    const float* W2    = (const float*)d_in[4];
    const float* b2    = (const float*)d_in[5];
    const float* w_ih0 = (const float*)d_in[6];
    const float* w_hh0 = (const float*)d_in[7];
    const float* b_ih0 = (const float*)d_in[8];
    const float* b_hh0 = (const float*)d_in[9];
    const float* w_ih1 = (const float*)d_in[10];
    const float* w_hh1 = (const float*)d_in[11];
    const float* b_ih1 = (const float*)d_in[12];
    const float* b_hh1 = (const float*)d_in[13];
    float* out = (float*)d_out;

    const int SMEM_GEMM = SA_B + SB_B;

    cudaFuncSetAttribute(gcn_kernel, cudaFuncAttributeMaxDynamicSharedMemorySize, SMEM_GCN);
    cudaFuncSetAttribute(gemm_gi0_kernel, cudaFuncAttributeMaxDynamicSharedMemorySize, SMEM_GEMM);
    cudaFuncSetAttribute(gru_persist_kernel, cudaFuncAttributeMaxDynamicSharedMemorySize, GRU_SMEM);

    prep_kernel<<<PREP_CTAS, 256>>>(ei);
    gcn_kernel<<<GCN_CTAS + WCONV_CTAS, 1024, SMEM_GCN>>>(x, W1, b1, W2, b2, w_ih0, b_ih0);
    gemm_gi0_kernel<<<dim3(MP / 64, G3 / 128, KSPL), 256, SMEM_GEMM>>>();
    gru_persist_kernel<<<96, 256, GRU_SMEM>>>(w_hh0, b_hh0, w_ih1, b_ih1,
                                              w_hh1, b_hh1, out);   // capture slot #4
}